// round 1
// baseline (speedup 1.0000x reference)
#include <cuda_runtime.h>

#define NN 100000
#define NE 1600000
#define NG 512
#define F  128
#define NCONV 4

// ---------------- scratch (device globals; no allocation) ----------------
__device__ float g_bufA[NN * F];   // g = (x@W) * dinv[row]
__device__ float g_bufB[NN * F];   // agg accumulator, then next-layer x (in place)
__device__ float g_deg[NN];
__device__ float g_dinv[NN];
__device__ float g_gsum[NG * F];
__device__ float g_gcnt[NG];

// ---------------- utility ----------------
__global__ void fill_zero(float* __restrict__ p, int n4) {
    int i = blockIdx.x * blockDim.x + threadIdx.x;
    if (i < n4) reinterpret_cast<float4*>(p)[i] = make_float4(0.f, 0.f, 0.f, 0.f);
}

__global__ void deg_kernel(const int* __restrict__ ei, float* __restrict__ deg) {
    int e = blockIdx.x * blockDim.x + threadIdx.x;
    if (e < NE) atomicAdd(&deg[ei[NE + e]], 1.0f);
}

__global__ void dinv_kernel(const float* __restrict__ deg, float* __restrict__ dinv) {
    int i = blockIdx.x * blockDim.x + threadIdx.x;
    if (i < NN) dinv[i] = rsqrtf(deg[i] + 2.0f);   // improved=True: +2 self-loop weight
}

// ---------------- scaled GEMM: out[r][c] = dinv[r] * sum_k X[r][k] * W[k][c] ----------------
// 256 threads/block, 32 rows/block (100000 = 3125 * 32, exact), full W in dyn smem.
#define GEMM_SMEM ((F * F + 32 * F) * 4)   // 81920 bytes

__global__ void gemm_scaled(const float* __restrict__ X, const float* __restrict__ W,
                            const float* __restrict__ dinv, float* __restrict__ out) {
    extern __shared__ float sm[];
    float* ws = sm;                 // [128][128]
    float* xs = sm + F * F;         // [32][128]
    const int t = threadIdx.x;
    const int row0 = blockIdx.x * 32;

    const float4* W4 = reinterpret_cast<const float4*>(W);
    float4* ws4 = reinterpret_cast<float4*>(ws);
    #pragma unroll
    for (int i = t; i < (F * F) / 4; i += 256) ws4[i] = W4[i];

    const float4* X4 = reinterpret_cast<const float4*>(X + (size_t)row0 * F);
    float4* xs4 = reinterpret_cast<float4*>(xs);
    #pragma unroll
    for (int i = t; i < (32 * F) / 4; i += 256) xs4[i] = X4[i];
    __syncthreads();

    const int c4 = t & 31;        // which float4 of the 128 output cols
    const int w  = t >> 5;        // warp id 0..7 -> rows 4w..4w+3
    const int r  = w * 4;
    const float* xp = xs + r * F;

    float4 a0 = make_float4(0.f, 0.f, 0.f, 0.f), a1 = a0, a2 = a0, a3 = a0;

    #pragma unroll 8
    for (int k = 0; k < F; k++) {
        float4 wv = ws4[k * 32 + c4];
        float x0 = xp[k];
        float x1 = xp[F + k];
        float x2 = xp[2 * F + k];
        float x3 = xp[3 * F + k];
        a0.x += x0 * wv.x; a0.y += x0 * wv.y; a0.z += x0 * wv.z; a0.w += x0 * wv.w;
        a1.x += x1 * wv.x; a1.y += x1 * wv.y; a1.z += x1 * wv.z; a1.w += x1 * wv.w;
        a2.x += x2 * wv.x; a2.y += x2 * wv.y; a2.z += x2 * wv.z; a2.w += x2 * wv.w;
        a3.x += x3 * wv.x; a3.y += x3 * wv.y; a3.z += x3 * wv.z; a3.w += x3 * wv.w;
    }

    float d0 = dinv[row0 + r + 0];
    float d1 = dinv[row0 + r + 1];
    float d2 = dinv[row0 + r + 2];
    float d3 = dinv[row0 + r + 3];
    float4* O4 = reinterpret_cast<float4*>(out);
    O4[(size_t)(row0 + r + 0) * 32 + c4] = make_float4(a0.x * d0, a0.y * d0, a0.z * d0, a0.w * d0);
    O4[(size_t)(row0 + r + 1) * 32 + c4] = make_float4(a1.x * d1, a1.y * d1, a1.z * d1, a1.w * d1);
    O4[(size_t)(row0 + r + 2) * 32 + c4] = make_float4(a2.x * d2, a2.y * d2, a2.z * d2, a2.w * d2);
    O4[(size_t)(row0 + r + 3) * 32 + c4] = make_float4(a3.x * d3, a3.y * d3, a3.z * d3, a3.w * d3);
}

// ---------------- edge scatter: agg[dst] += g[src]  (warp per edge, red.v4) ----------------
__global__ void scatter_kernel(const int* __restrict__ ei, const float* __restrict__ g,
                               float* __restrict__ agg) {
    int widx = (blockIdx.x * blockDim.x + threadIdx.x) >> 5;
    int lane = threadIdx.x & 31;
    if (widx >= NE) return;
    int src = ei[widx];
    int dst = ei[NE + widx];
    float4 v = reinterpret_cast<const float4*>(g)[(size_t)src * 32 + lane];
    float* p = agg + (size_t)dst * F + lane * 4;
    asm volatile("red.global.add.v4.f32 [%0], {%1, %2, %3, %4};"
                 :: "l"(p), "f"(v.x), "f"(v.y), "f"(v.z), "f"(v.w) : "memory");
}

// ---------------- combine: x_next = relu(dinv*agg + 2*dinv*g + b), in place into agg ----------------
__global__ void combine_kernel(float* __restrict__ agg, const float* __restrict__ g,
                               const float* __restrict__ dinv, const float* __restrict__ bias) {
    int i4 = blockIdx.x * blockDim.x + threadIdx.x;
    if (i4 >= NN * 32) return;
    int n  = i4 >> 5;
    int fq = i4 & 31;
    float dv = dinv[n];
    float4 a = reinterpret_cast<float4*>(agg)[i4];
    float4 s = reinterpret_cast<const float4*>(g)[i4];
    float4 b = reinterpret_cast<const float4*>(bias)[fq];
    float4 r;
    r.x = fmaxf(dv * a.x + 2.f * dv * s.x + b.x, 0.f);
    r.y = fmaxf(dv * a.y + 2.f * dv * s.y + b.y, 0.f);
    r.z = fmaxf(dv * a.z + 2.f * dv * s.z + b.z, 0.f);
    r.w = fmaxf(dv * a.w + 2.f * dv * s.w + b.w, 0.f);
    reinterpret_cast<float4*>(agg)[i4] = r;
}

// ---------------- pooling: run-length accumulate over sorted batch ----------------
__global__ void pool_kernel(const float* __restrict__ x, const int* __restrict__ batch,
                            float* __restrict__ gsum) {
    int f  = threadIdx.x;            // 128
    int n0 = blockIdx.x * 64;
    if (n0 >= NN) return;
    int nend = min(n0 + 64, NN);
    int cur = batch[n0];
    float acc = 0.f;
    for (int n = n0; n < nend; n++) {
        int b = batch[n];
        if (b != cur) { atomicAdd(&gsum[cur * F + f], acc); acc = 0.f; cur = b; }
        acc += x[(size_t)n * F + f];
    }
    atomicAdd(&gsum[cur * F + f], acc);
}

__global__ void cnt_kernel(const int* __restrict__ batch, float* __restrict__ gcnt) {
    int n = blockIdx.x * blockDim.x + threadIdx.x;
    if (n < NN) atomicAdd(&gcnt[batch[n]], 1.0f);
}

// ---------------- MLP head: one block per graph ----------------
__global__ void head_kernel(const float* __restrict__ gsum, const float* __restrict__ gcnt,
                            const float* __restrict__ fc1w, const float* __restrict__ fc1b,
                            const float* __restrict__ fc2w, const float* __restrict__ fc2b,
                            float* __restrict__ out) {
    int gI = blockIdx.x;
    int f  = threadIdx.x;            // 128
    __shared__ float pooled[F];
    __shared__ float red[F];
    float cnt = fmaxf(gcnt[gI], 1.0f);
    pooled[f] = gsum[gI * F + f] / cnt;
    __syncthreads();
    float a = fc1b[f];
    #pragma unroll 8
    for (int k = 0; k < F; k++) a += pooled[k] * fc1w[k * F + f];
    red[f] = fmaxf(a, 0.f) * fc2w[f];
    __syncthreads();
    #pragma unroll
    for (int s = 64; s > 0; s >>= 1) {
        if (f < s) red[f] += red[f + s];
        __syncthreads();
    }
    if (f == 0) out[gI] = red[0] + fc2b[0];
}

// ---------------- launch ----------------
extern "C" void kernel_launch(void* const* d_in, const int* in_sizes, int n_in,
                              void* d_out, int out_size) {
    const float* x      = (const float*)d_in[0];
    const int*   ei     = (const int*)d_in[1];
    const int*   batch  = (const int*)d_in[2];
    const float* conv_w = (const float*)d_in[4];
    const float* conv_b = (const float*)d_in[5];
    const float* fc1w   = (const float*)d_in[6];
    const float* fc1b   = (const float*)d_in[7];
    const float* fc2w   = (const float*)d_in[8];
    const float* fc2b   = (const float*)d_in[9];
    float* out = (float*)d_out;

    float *bufA, *bufB, *deg, *dinv, *gsum, *gcnt;
    cudaGetSymbolAddress((void**)&bufA, g_bufA);
    cudaGetSymbolAddress((void**)&bufB, g_bufB);
    cudaGetSymbolAddress((void**)&deg,  g_deg);
    cudaGetSymbolAddress((void**)&dinv, g_dinv);
    cudaGetSymbolAddress((void**)&gsum, g_gsum);
    cudaGetSymbolAddress((void**)&gcnt, g_gcnt);

    cudaFuncSetAttribute(gemm_scaled, cudaFuncAttributeMaxDynamicSharedMemorySize, GEMM_SMEM);

    // degree + dinv
    fill_zero<<<(NN / 4 + 255) / 256, 256>>>(deg, NN / 4);
    deg_kernel<<<(NE + 255) / 256, 256>>>(ei, deg);
    dinv_kernel<<<(NN + 255) / 256, 256>>>(deg, dinv);

    const float* X = x;
    for (int l = 0; l < NCONV; l++) {
        gemm_scaled<<<NN / 32, 256, GEMM_SMEM>>>(X, conv_w + (size_t)l * F * F, dinv, bufA);
        fill_zero<<<(NN * F / 4 + 255) / 256, 256>>>(bufB, NN * F / 4);
        scatter_kernel<<<NE / 8, 256>>>(ei, bufA, bufB);
        combine_kernel<<<(NN * 32 + 255) / 256, 256>>>(bufB, bufA, dinv, conv_b + (size_t)l * F);
        X = bufB;
    }

    // global mean pool
    fill_zero<<<(NG * F / 4 + 255) / 256, 256>>>(gsum, NG * F / 4);
    fill_zero<<<1, 128>>>(gcnt, NG / 4);
    pool_kernel<<<(NN + 63) / 64, 128>>>(bufB, batch, gsum);
    cnt_kernel<<<(NN + 255) / 256, 256>>>(batch, gcnt);

    // head
    head_kernel<<<NG, 128>>>(gsum, gcnt, fc1w, fc1b, fc2w, fc2b, out);
}

// round 2
// speedup vs baseline: 1.5657x; 1.5657x over previous
#include <cuda_runtime.h>

#define NN 100000
#define NE 1600000
#define NG 512
#define F  128
#define NCONV 4

typedef unsigned long long ull;

// ---------------- scratch (device globals; no allocation) ----------------
__device__ float g_bufA[NN * F];   // g = (x@W) * dinv[row]
__device__ float g_bufB[NN * F];   // x_next (written fully by gather_combine)
__device__ int   g_cnt[NN];
__device__ int   g_rowptr[NN + 1];
__device__ int   g_cursor[NN];
__device__ int   g_csr[NE];
__device__ int   g_blksum[128];
__device__ int   g_blkoff[128];
__device__ float g_dinv[NN];
__device__ float g_gsum[NG * F];
__device__ float g_gcnt[NG];

// ---------------- utility ----------------
__global__ void fill_zero(float* __restrict__ p, int n4) {
    int i = blockIdx.x * blockDim.x + threadIdx.x;
    if (i < n4) reinterpret_cast<float4*>(p)[i] = make_float4(0.f, 0.f, 0.f, 0.f);
}

__global__ void count_kernel(const int* __restrict__ ei, int* __restrict__ cnt) {
    int e = blockIdx.x * blockDim.x + threadIdx.x;
    if (e < NE) atomicAdd(&cnt[ei[NE + e]], 1);
}

__global__ void dinv_kernel(const int* __restrict__ cnt, float* __restrict__ dinv) {
    int i = blockIdx.x * blockDim.x + threadIdx.x;
    if (i < NN) dinv[i] = rsqrtf((float)cnt[i] + 2.0f);   // improved=True self-loop weight 2
}

// ---------------- CSR build: scan over counts ----------------
__global__ void scan1(const int* __restrict__ cnt, int* __restrict__ rowptr,
                      int* __restrict__ blksum) {
    __shared__ int s[1024];
    int i = blockIdx.x * 1024 + threadIdx.x;
    int v = (i < NN) ? cnt[i] : 0;
    s[threadIdx.x] = v;
    __syncthreads();
    #pragma unroll
    for (int off = 1; off < 1024; off <<= 1) {
        int t = (threadIdx.x >= off) ? s[threadIdx.x - off] : 0;
        __syncthreads();
        s[threadIdx.x] += t;
        __syncthreads();
    }
    if (i < NN) rowptr[i + 1] = s[threadIdx.x];
    if (threadIdx.x == 1023) blksum[blockIdx.x] = s[1023];
    if (i == 0) rowptr[0] = 0;
}

__global__ void scan2(const int* __restrict__ blksum, int* __restrict__ blkoff, int nb) {
    __shared__ int s[128];
    int t = threadIdx.x;
    s[t] = (t < nb) ? blksum[t] : 0;
    __syncthreads();
    #pragma unroll
    for (int off = 1; off < 128; off <<= 1) {
        int v = (t >= off) ? s[t - off] : 0;
        __syncthreads();
        s[t] += v;
        __syncthreads();
    }
    if (t < nb) blkoff[t] = (t == 0) ? 0 : s[t - 1];
}

__global__ void scan3(int* __restrict__ rowptr, const int* __restrict__ blkoff,
                      int* __restrict__ cursor) {
    int j = blockIdx.x * blockDim.x + threadIdx.x + 1;   // 1..NN
    if (j <= NN) {
        int v = rowptr[j] + blkoff[(j - 1) >> 10];
        rowptr[j] = v;
        if (j < NN) cursor[j] = v;
    }
    if (j == 1) cursor[0] = 0;
}

__global__ void csr_fill(const int* __restrict__ ei, int* __restrict__ cursor,
                         int* __restrict__ csr) {
    int e = blockIdx.x * blockDim.x + threadIdx.x;
    if (e >= NE) return;
    int dst = ei[NE + e];
    int pos = atomicAdd(&cursor[dst], 1);
    csr[pos] = ei[e];
}

// ---------------- scaled GEMM (f32x2 packed): out[r][c] = dinv[r]*sum_k X[r][k]*W[k][c] ----
// 256 threads, 32 rows/block (100000 = 3125*32). W normal in smem (64KB),
// X tile duplicated-pair in smem (32KB): LDS.64 yields (x,x) for fma.rn.f32x2.
#define GEMM_SMEM ((F * F) * 4 + (32 * F) * 8)   // 98304 bytes

__device__ __forceinline__ void ffma2(ull& d, ull a, ull b) {
    asm("fma.rn.f32x2 %0, %1, %2, %0;" : "+l"(d) : "l"(a), "l"(b));
}
__device__ __forceinline__ void unpk2(ull p, float& lo, float& hi) {
    asm("mov.b64 {%0, %1}, %2;" : "=f"(lo), "=f"(hi) : "l"(p));
}

__global__ void gemm_scaled(const float* __restrict__ X, const float* __restrict__ W,
                            const float* __restrict__ dinv, float* __restrict__ out) {
    extern __shared__ float sm[];
    float* ws = sm;                            // [128][128] floats
    ull* xsd = (ull*)(sm + F * F);             // [32][128] duplicated pairs
    const int t = threadIdx.x;
    const int row0 = blockIdx.x * 32;

    const float4* W4 = reinterpret_cast<const float4*>(W);
    float4* ws4 = reinterpret_cast<float4*>(ws);
    #pragma unroll
    for (int i = t; i < (F * F) / 4; i += 256) ws4[i] = W4[i];

    const float4* X4 = reinterpret_cast<const float4*>(X + (size_t)row0 * F);
    #pragma unroll
    for (int i = t; i < (32 * F) / 4; i += 256) {
        float4 v = X4[i];
        ull p0, p1, p2, p3;
        asm("mov.b64 %0, {%1, %1};" : "=l"(p0) : "f"(v.x));
        asm("mov.b64 %0, {%1, %1};" : "=l"(p1) : "f"(v.y));
        asm("mov.b64 %0, {%1, %1};" : "=l"(p2) : "f"(v.z));
        asm("mov.b64 %0, {%1, %1};" : "=l"(p3) : "f"(v.w));
        xsd[i * 4 + 0] = p0; xsd[i * 4 + 1] = p1;
        xsd[i * 4 + 2] = p2; xsd[i * 4 + 3] = p3;
    }
    __syncthreads();

    const int c4 = t & 31;        // which float4 (= pair of f32x2) of 128 cols
    const int w  = t >> 5;        // warp id 0..7 -> rows 4w..4w+3
    const int r  = w * 4;
    const ull* xp = xsd + r * F;
    const ulonglong2* wsu = reinterpret_cast<const ulonglong2*>(ws);

    ull a00 = 0, a01 = 0, a10 = 0, a11 = 0, a20 = 0, a21 = 0, a30 = 0, a31 = 0;

    #pragma unroll 8
    for (int k = 0; k < F; k++) {
        ulonglong2 wv = wsu[k * 32 + c4];
        ull x0 = xp[k];
        ull x1 = xp[F + k];
        ull x2 = xp[2 * F + k];
        ull x3 = xp[3 * F + k];
        ffma2(a00, x0, wv.x); ffma2(a01, x0, wv.y);
        ffma2(a10, x1, wv.x); ffma2(a11, x1, wv.y);
        ffma2(a20, x2, wv.x); ffma2(a21, x2, wv.y);
        ffma2(a30, x3, wv.x); ffma2(a31, x3, wv.y);
    }

    float4* O4 = reinterpret_cast<float4*>(out);
    float d0 = dinv[row0 + r + 0];
    float d1 = dinv[row0 + r + 1];
    float d2 = dinv[row0 + r + 2];
    float d3 = dinv[row0 + r + 3];
    float4 o;
    unpk2(a00, o.x, o.y); unpk2(a01, o.z, o.w);
    O4[(size_t)(row0 + r + 0) * 32 + c4] = make_float4(o.x * d0, o.y * d0, o.z * d0, o.w * d0);
    unpk2(a10, o.x, o.y); unpk2(a11, o.z, o.w);
    O4[(size_t)(row0 + r + 1) * 32 + c4] = make_float4(o.x * d1, o.y * d1, o.z * d1, o.w * d1);
    unpk2(a20, o.x, o.y); unpk2(a21, o.z, o.w);
    O4[(size_t)(row0 + r + 2) * 32 + c4] = make_float4(o.x * d2, o.y * d2, o.z * d2, o.w * d2);
    unpk2(a30, o.x, o.y); unpk2(a31, o.z, o.w);
    O4[(size_t)(row0 + r + 3) * 32 + c4] = make_float4(o.x * d3, o.y * d3, o.z * d3, o.w * d3);
}

// ---------------- gather + combine: one warp per node ----------------
// x_next[n] = relu( dinv[n] * sum_{e in in(n)} g[src_e] + 2*dinv[n]*g[n] + b )
__global__ void gather_combine(const int* __restrict__ rowptr, const int* __restrict__ csr,
                               const float* __restrict__ g, const float* __restrict__ dinv,
                               const float* __restrict__ bias, float* __restrict__ out) {
    int n = (blockIdx.x * blockDim.x + threadIdx.x) >> 5;
    int lane = threadIdx.x & 31;
    if (n >= NN) return;
    int start = rowptr[n];
    int end   = rowptr[n + 1];

    const float4* g4 = reinterpret_cast<const float4*>(g);
    float4 acc0 = make_float4(0.f, 0.f, 0.f, 0.f);
    float4 acc1 = make_float4(0.f, 0.f, 0.f, 0.f);

    for (int base = start; base < end; base += 32) {
        int m = min(32, end - base);
        int s = (lane < m) ? csr[base + lane] : 0;
        int j = 0;
        for (; j + 1 < m; j += 2) {
            int s0 = __shfl_sync(0xffffffffu, s, j);
            int s1 = __shfl_sync(0xffffffffu, s, j + 1);
            float4 v0 = g4[(size_t)s0 * 32 + lane];
            float4 v1 = g4[(size_t)s1 * 32 + lane];
            acc0.x += v0.x; acc0.y += v0.y; acc0.z += v0.z; acc0.w += v0.w;
            acc1.x += v1.x; acc1.y += v1.y; acc1.z += v1.z; acc1.w += v1.w;
        }
        if (j < m) {
            int s0 = __shfl_sync(0xffffffffu, s, j);
            float4 v0 = g4[(size_t)s0 * 32 + lane];
            acc0.x += v0.x; acc0.y += v0.y; acc0.z += v0.z; acc0.w += v0.w;
        }
    }

    float dv = dinv[n];
    float4 self = g4[(size_t)n * 32 + lane];
    float4 b = reinterpret_cast<const float4*>(bias)[lane];
    float4 r;
    r.x = fmaxf(dv * (acc0.x + acc1.x + 2.f * self.x) + b.x, 0.f);
    r.y = fmaxf(dv * (acc0.y + acc1.y + 2.f * self.y) + b.y, 0.f);
    r.z = fmaxf(dv * (acc0.z + acc1.z + 2.f * self.z) + b.z, 0.f);
    r.w = fmaxf(dv * (acc0.w + acc1.w + 2.f * self.w) + b.w, 0.f);
    reinterpret_cast<float4*>(out)[(size_t)n * 32 + lane] = r;
}

// ---------------- pooling: run-length accumulate over sorted batch ----------------
__global__ void pool_kernel(const float* __restrict__ x, const int* __restrict__ batch,
                            float* __restrict__ gsum) {
    int f  = threadIdx.x;            // 128
    int n0 = blockIdx.x * 64;
    if (n0 >= NN) return;
    int nend = min(n0 + 64, NN);
    int cur = batch[n0];
    float acc = 0.f;
    for (int n = n0; n < nend; n++) {
        int b = batch[n];
        if (b != cur) { atomicAdd(&gsum[cur * F + f], acc); acc = 0.f; cur = b; }
        acc += x[(size_t)n * F + f];
    }
    atomicAdd(&gsum[cur * F + f], acc);
}

__global__ void cnt_kernel(const int* __restrict__ batch, float* __restrict__ gcnt) {
    int n = blockIdx.x * blockDim.x + threadIdx.x;
    if (n < NN) atomicAdd(&gcnt[batch[n]], 1.0f);
}

// ---------------- MLP head: one block per graph ----------------
__global__ void head_kernel(const float* __restrict__ gsum, const float* __restrict__ gcnt,
                            const float* __restrict__ fc1w, const float* __restrict__ fc1b,
                            const float* __restrict__ fc2w, const float* __restrict__ fc2b,
                            float* __restrict__ out) {
    int gI = blockIdx.x;
    int f  = threadIdx.x;            // 128
    __shared__ float pooled[F];
    __shared__ float red[F];
    float cnt = fmaxf(gcnt[gI], 1.0f);
    pooled[f] = gsum[gI * F + f] / cnt;
    __syncthreads();
    float a = fc1b[f];
    #pragma unroll 8
    for (int k = 0; k < F; k++) a += pooled[k] * fc1w[k * F + f];
    red[f] = fmaxf(a, 0.f) * fc2w[f];
    __syncthreads();
    #pragma unroll
    for (int s = 64; s > 0; s >>= 1) {
        if (f < s) red[f] += red[f + s];
        __syncthreads();
    }
    if (f == 0) out[gI] = red[0] + fc2b[0];
}

// ---------------- launch ----------------
extern "C" void kernel_launch(void* const* d_in, const int* in_sizes, int n_in,
                              void* d_out, int out_size) {
    const float* x      = (const float*)d_in[0];
    const int*   ei     = (const int*)d_in[1];
    const int*   batch  = (const int*)d_in[2];
    const float* conv_w = (const float*)d_in[4];
    const float* conv_b = (const float*)d_in[5];
    const float* fc1w   = (const float*)d_in[6];
    const float* fc1b   = (const float*)d_in[7];
    const float* fc2w   = (const float*)d_in[8];
    const float* fc2b   = (const float*)d_in[9];
    float* out = (float*)d_out;

    float *bufA, *bufB, *dinv, *gsum, *gcnt;
    int *cnt, *rowptr, *cursor, *csr, *blksum, *blkoff;
    cudaGetSymbolAddress((void**)&bufA,   g_bufA);
    cudaGetSymbolAddress((void**)&bufB,   g_bufB);
    cudaGetSymbolAddress((void**)&cnt,    g_cnt);
    cudaGetSymbolAddress((void**)&rowptr, g_rowptr);
    cudaGetSymbolAddress((void**)&cursor, g_cursor);
    cudaGetSymbolAddress((void**)&csr,    g_csr);
    cudaGetSymbolAddress((void**)&blksum, g_blksum);
    cudaGetSymbolAddress((void**)&blkoff, g_blkoff);
    cudaGetSymbolAddress((void**)&dinv,   g_dinv);
    cudaGetSymbolAddress((void**)&gsum,   g_gsum);
    cudaGetSymbolAddress((void**)&gcnt,   g_gcnt);

    cudaFuncSetAttribute(gemm_scaled, cudaFuncAttributeMaxDynamicSharedMemorySize, GEMM_SMEM);

    const int NB_SCAN = (NN + 1023) / 1024;   // 98

    // degree counts + CSR build + dinv
    fill_zero<<<(NN / 4 + 255) / 256, 256>>>((float*)cnt, NN / 4);
    count_kernel<<<(NE + 255) / 256, 256>>>(ei, cnt);
    scan1<<<NB_SCAN, 1024>>>(cnt, rowptr, blksum);
    scan2<<<1, 128>>>(blksum, blkoff, NB_SCAN);
    scan3<<<(NN + 255) / 256, 256>>>(rowptr, blkoff, cursor);
    csr_fill<<<(NE + 255) / 256, 256>>>(ei, cursor, csr);
    dinv_kernel<<<(NN + 255) / 256, 256>>>(cnt, dinv);

    const float* X = x;
    for (int l = 0; l < NCONV; l++) {
        gemm_scaled<<<NN / 32, 256, GEMM_SMEM>>>(X, conv_w + (size_t)l * F * F, dinv, bufA);
        gather_combine<<<(NN * 32 + 255) / 256, 256>>>(rowptr, csr, bufA, dinv,
                                                       conv_b + (size_t)l * F, bufB);
        X = bufB;
    }

    // global mean pool
    fill_zero<<<(NG * F / 4 + 255) / 256, 256>>>(gsum, NG * F / 4);
    fill_zero<<<1, 128>>>(gcnt, NG / 4);
    pool_kernel<<<(NN + 63) / 64, 128>>>(bufB, batch, gsum);
    cnt_kernel<<<(NN + 255) / 256, 256>>>(batch, gcnt);

    // head
    head_kernel<<<NG, 128>>>(gsum, gcnt, fc1w, fc1b, fc2w, fc2b, out);
}

// round 3
// speedup vs baseline: 1.7273x; 1.1032x over previous
#include <cuda_runtime.h>

#define NN 100000
#define NE 1600000
#define NG 512
#define F  128
#define NCONV 4

typedef unsigned long long ull;
typedef unsigned int uint;

// ---------------- scratch (device globals; no allocation) ----------------
__device__ uint  g_bufA[NN * (F / 2)];   // g = (x@W)*dinv[row], packed bf16x2 (25.6MB)
__device__ float g_bufB[NN * F];         // x_next fp32
__device__ int   g_cnt[NN];
__device__ int   g_rowptr[NN + 1];
__device__ int   g_cursor[NN];
__device__ int   g_csr[NE];
__device__ int   g_blksum[128];
__device__ int   g_blkoff[128];
__device__ float g_dinv[NN];
__device__ float g_gsum[NG * F];
__device__ float g_gcnt[NG];

// ---------------- utility ----------------
__global__ void fill_zero(float* __restrict__ p, int n4) {
    int i = blockIdx.x * blockDim.x + threadIdx.x;
    if (i < n4) reinterpret_cast<float4*>(p)[i] = make_float4(0.f, 0.f, 0.f, 0.f);
}

__global__ void count_kernel(const int* __restrict__ ei, int* __restrict__ cnt) {
    int e = blockIdx.x * blockDim.x + threadIdx.x;
    if (e < NE) atomicAdd(&cnt[ei[NE + e]], 1);
}

// ---------------- CSR build: scan over counts (dinv fused into scan1) ----------------
__global__ void scan1(const int* __restrict__ cnt, int* __restrict__ rowptr,
                      int* __restrict__ blksum, float* __restrict__ dinv) {
    __shared__ int s[1024];
    int i = blockIdx.x * 1024 + threadIdx.x;
    int v = (i < NN) ? cnt[i] : 0;
    if (i < NN) dinv[i] = rsqrtf((float)v + 2.0f);   // improved=True self-loop weight 2
    s[threadIdx.x] = v;
    __syncthreads();
    #pragma unroll
    for (int off = 1; off < 1024; off <<= 1) {
        int t = (threadIdx.x >= off) ? s[threadIdx.x - off] : 0;
        __syncthreads();
        s[threadIdx.x] += t;
        __syncthreads();
    }
    if (i < NN) rowptr[i + 1] = s[threadIdx.x];
    if (threadIdx.x == 1023) blksum[blockIdx.x] = s[1023];
    if (i == 0) rowptr[0] = 0;
}

__global__ void scan2(const int* __restrict__ blksum, int* __restrict__ blkoff, int nb) {
    __shared__ int s[128];
    int t = threadIdx.x;
    s[t] = (t < nb) ? blksum[t] : 0;
    __syncthreads();
    #pragma unroll
    for (int off = 1; off < 128; off <<= 1) {
        int v = (t >= off) ? s[t - off] : 0;
        __syncthreads();
        s[t] += v;
        __syncthreads();
    }
    if (t < nb) blkoff[t] = (t == 0) ? 0 : s[t - 1];
}

__global__ void scan3(int* __restrict__ rowptr, const int* __restrict__ blkoff,
                      int* __restrict__ cursor) {
    int j = blockIdx.x * blockDim.x + threadIdx.x + 1;   // 1..NN
    if (j <= NN) {
        int v = rowptr[j] + blkoff[(j - 1) >> 10];
        rowptr[j] = v;
        if (j < NN) cursor[j] = v;
    }
    if (j == 1) cursor[0] = 0;
}

__global__ void csr_fill(const int* __restrict__ ei, int* __restrict__ cursor,
                         int* __restrict__ csr) {
    int e = blockIdx.x * blockDim.x + threadIdx.x;
    if (e >= NE) return;
    int dst = ei[NE + e];
    int pos = atomicAdd(&cursor[dst], 1);
    csr[pos] = ei[e];
}

// ---------------- packed bf16 helpers ----------------
__device__ __forceinline__ uint pk_bf16x2(float lo, float hi) {
    uint r;
    asm("cvt.rn.bf16x2.f32 %0, %1, %2;" : "=r"(r) : "f"(hi), "f"(lo));
    return r;
}
__device__ __forceinline__ float4 bf4(uint2 p) {
    float4 v;
    v.x = __uint_as_float(p.x << 16);
    v.y = __uint_as_float(p.x & 0xffff0000u);
    v.z = __uint_as_float(p.y << 16);
    v.w = __uint_as_float(p.y & 0xffff0000u);
    return v;
}

// ---------------- scaled GEMM (f32x2 packed), bf16 packed output ----------------
// out_bf[r][c] = bf16( dinv[r] * sum_k X[r][k] * W[k][c] )
#define GEMM_SMEM ((F * F) * 4 + (32 * F) * 8)   // 98304 bytes

__device__ __forceinline__ void ffma2(ull& d, ull a, ull b) {
    asm("fma.rn.f32x2 %0, %1, %2, %0;" : "+l"(d) : "l"(a), "l"(b));
}
__device__ __forceinline__ void unpk2(ull p, float& lo, float& hi) {
    asm("mov.b64 {%0, %1}, %2;" : "=f"(lo), "=f"(hi) : "l"(p));
}

__global__ void gemm_scaled(const float* __restrict__ X, const float* __restrict__ W,
                            const float* __restrict__ dinv, uint* __restrict__ out) {
    extern __shared__ float sm[];
    float* ws = sm;                            // [128][128] floats
    ull* xsd = (ull*)(sm + F * F);             // [32][128] duplicated pairs
    const int t = threadIdx.x;
    const int row0 = blockIdx.x * 32;

    const float4* W4 = reinterpret_cast<const float4*>(W);
    float4* ws4 = reinterpret_cast<float4*>(ws);
    #pragma unroll
    for (int i = t; i < (F * F) / 4; i += 256) ws4[i] = W4[i];

    const float4* X4 = reinterpret_cast<const float4*>(X + (size_t)row0 * F);
    #pragma unroll
    for (int i = t; i < (32 * F) / 4; i += 256) {
        float4 v = X4[i];
        ull p0, p1, p2, p3;
        asm("mov.b64 %0, {%1, %1};" : "=l"(p0) : "f"(v.x));
        asm("mov.b64 %0, {%1, %1};" : "=l"(p1) : "f"(v.y));
        asm("mov.b64 %0, {%1, %1};" : "=l"(p2) : "f"(v.z));
        asm("mov.b64 %0, {%1, %1};" : "=l"(p3) : "f"(v.w));
        xsd[i * 4 + 0] = p0; xsd[i * 4 + 1] = p1;
        xsd[i * 4 + 2] = p2; xsd[i * 4 + 3] = p3;
    }
    __syncthreads();

    const int c4 = t & 31;        // which group of 4 output cols
    const int w  = t >> 5;        // warp id 0..7 -> rows 4w..4w+3
    const int r  = w * 4;
    const ull* xp = xsd + r * F;
    const ulonglong2* wsu = reinterpret_cast<const ulonglong2*>(ws);

    ull a00 = 0, a01 = 0, a10 = 0, a11 = 0, a20 = 0, a21 = 0, a30 = 0, a31 = 0;

    #pragma unroll 8
    for (int k = 0; k < F; k++) {
        ulonglong2 wv = wsu[k * 32 + c4];
        ull x0 = xp[k];
        ull x1 = xp[F + k];
        ull x2 = xp[2 * F + k];
        ull x3 = xp[3 * F + k];
        ffma2(a00, x0, wv.x); ffma2(a01, x0, wv.y);
        ffma2(a10, x1, wv.x); ffma2(a11, x1, wv.y);
        ffma2(a20, x2, wv.x); ffma2(a21, x2, wv.y);
        ffma2(a30, x3, wv.x); ffma2(a31, x3, wv.y);
    }

    uint2* O2 = reinterpret_cast<uint2*>(out);
    float d0 = dinv[row0 + r + 0];
    float d1 = dinv[row0 + r + 1];
    float d2 = dinv[row0 + r + 2];
    float d3 = dinv[row0 + r + 3];
    float4 o;
    unpk2(a00, o.x, o.y); unpk2(a01, o.z, o.w);
    O2[(size_t)(row0 + r + 0) * 32 + c4] =
        make_uint2(pk_bf16x2(o.x * d0, o.y * d0), pk_bf16x2(o.z * d0, o.w * d0));
    unpk2(a10, o.x, o.y); unpk2(a11, o.z, o.w);
    O2[(size_t)(row0 + r + 1) * 32 + c4] =
        make_uint2(pk_bf16x2(o.x * d1, o.y * d1), pk_bf16x2(o.z * d1, o.w * d1));
    unpk2(a20, o.x, o.y); unpk2(a21, o.z, o.w);
    O2[(size_t)(row0 + r + 2) * 32 + c4] =
        make_uint2(pk_bf16x2(o.x * d2, o.y * d2), pk_bf16x2(o.z * d2, o.w * d2));
    unpk2(a30, o.x, o.y); unpk2(a31, o.z, o.w);
    O2[(size_t)(row0 + r + 3) * 32 + c4] =
        make_uint2(pk_bf16x2(o.x * d3, o.y * d3), pk_bf16x2(o.z * d3, o.w * d3));
}

// ---------------- gather + combine: one warp per node, bf16 messages ----------------
// x_next[n] = relu( dinv[n] * (sum_{e in in(n)} g[src_e] + 2*g[n]) + b )
__global__ void gather_combine(const int* __restrict__ rowptr, const int* __restrict__ csr,
                               const uint* __restrict__ g, const float* __restrict__ dinv,
                               const float* __restrict__ bias, float* __restrict__ out) {
    int n = (blockIdx.x * blockDim.x + threadIdx.x) >> 5;
    int lane = threadIdx.x & 31;
    if (n >= NN) return;
    int start = rowptr[n];
    int end   = rowptr[n + 1];

    const uint2* g2 = reinterpret_cast<const uint2*>(g);
    float4 acc0 = make_float4(0.f, 0.f, 0.f, 0.f);
    float4 acc1 = make_float4(0.f, 0.f, 0.f, 0.f);

    for (int base = start; base < end; base += 32) {
        int m = min(32, end - base);
        int s = (lane < m) ? csr[base + lane] : 0;
        int j = 0;
        for (; j + 1 < m; j += 2) {
            int s0 = __shfl_sync(0xffffffffu, s, j);
            int s1 = __shfl_sync(0xffffffffu, s, j + 1);
            float4 v0 = bf4(g2[(size_t)s0 * 32 + lane]);
            float4 v1 = bf4(g2[(size_t)s1 * 32 + lane]);
            acc0.x += v0.x; acc0.y += v0.y; acc0.z += v0.z; acc0.w += v0.w;
            acc1.x += v1.x; acc1.y += v1.y; acc1.z += v1.z; acc1.w += v1.w;
        }
        if (j < m) {
            int s0 = __shfl_sync(0xffffffffu, s, j);
            float4 v0 = bf4(g2[(size_t)s0 * 32 + lane]);
            acc0.x += v0.x; acc0.y += v0.y; acc0.z += v0.z; acc0.w += v0.w;
        }
    }

    float dv = dinv[n];
    float4 self = bf4(g2[(size_t)n * 32 + lane]);
    float4 b = reinterpret_cast<const float4*>(bias)[lane];
    float4 r;
    r.x = fmaxf(dv * (acc0.x + acc1.x + 2.f * self.x) + b.x, 0.f);
    r.y = fmaxf(dv * (acc0.y + acc1.y + 2.f * self.y) + b.y, 0.f);
    r.z = fmaxf(dv * (acc0.z + acc1.z + 2.f * self.z) + b.z, 0.f);
    r.w = fmaxf(dv * (acc0.w + acc1.w + 2.f * self.w) + b.w, 0.f);
    reinterpret_cast<float4*>(out)[(size_t)n * 32 + lane] = r;
}

// ---------------- pooling: run-length accumulate over sorted batch ----------------
__global__ void pool_kernel(const float* __restrict__ x, const int* __restrict__ batch,
                            float* __restrict__ gsum) {
    int f  = threadIdx.x;            // 128
    int n0 = blockIdx.x * 64;
    if (n0 >= NN) return;
    int nend = min(n0 + 64, NN);
    int cur = batch[n0];
    float acc = 0.f;
    for (int n = n0; n < nend; n++) {
        int b = batch[n];
        if (b != cur) { atomicAdd(&gsum[cur * F + f], acc); acc = 0.f; cur = b; }
        acc += x[(size_t)n * F + f];
    }
    atomicAdd(&gsum[cur * F + f], acc);
}

__global__ void cnt_kernel(const int* __restrict__ batch, float* __restrict__ gcnt) {
    int n = blockIdx.x * blockDim.x + threadIdx.x;
    if (n < NN) atomicAdd(&gcnt[batch[n]], 1.0f);
}

// ---------------- MLP head: one block per graph ----------------
__global__ void head_kernel(const float* __restrict__ gsum, const float* __restrict__ gcnt,
                            const float* __restrict__ fc1w, const float* __restrict__ fc1b,
                            const float* __restrict__ fc2w, const float* __restrict__ fc2b,
                            float* __restrict__ out) {
    int gI = blockIdx.x;
    int f  = threadIdx.x;            // 128
    __shared__ float pooled[F];
    __shared__ float red[F];
    float cnt = fmaxf(gcnt[gI], 1.0f);
    pooled[f] = gsum[gI * F + f] / cnt;
    __syncthreads();
    float a = fc1b[f];
    #pragma unroll 8
    for (int k = 0; k < F; k++) a += pooled[k] * fc1w[k * F + f];
    red[f] = fmaxf(a, 0.f) * fc2w[f];
    __syncthreads();
    #pragma unroll
    for (int s = 64; s > 0; s >>= 1) {
        if (f < s) red[f] += red[f + s];
        __syncthreads();
    }
    if (f == 0) out[gI] = red[0] + fc2b[0];
}

// ---------------- launch ----------------
extern "C" void kernel_launch(void* const* d_in, const int* in_sizes, int n_in,
                              void* d_out, int out_size) {
    const float* x      = (const float*)d_in[0];
    const int*   ei     = (const int*)d_in[1];
    const int*   batch  = (const int*)d_in[2];
    const float* conv_w = (const float*)d_in[4];
    const float* conv_b = (const float*)d_in[5];
    const float* fc1w   = (const float*)d_in[6];
    const float* fc1b   = (const float*)d_in[7];
    const float* fc2w   = (const float*)d_in[8];
    const float* fc2b   = (const float*)d_in[9];
    float* out = (float*)d_out;

    float *bufB, *dinv, *gsum, *gcnt;
    uint *bufA;
    int *cnt, *rowptr, *cursor, *csr, *blksum, *blkoff;
    cudaGetSymbolAddress((void**)&bufA,   g_bufA);
    cudaGetSymbolAddress((void**)&bufB,   g_bufB);
    cudaGetSymbolAddress((void**)&cnt,    g_cnt);
    cudaGetSymbolAddress((void**)&rowptr, g_rowptr);
    cudaGetSymbolAddress((void**)&cursor, g_cursor);
    cudaGetSymbolAddress((void**)&csr,    g_csr);
    cudaGetSymbolAddress((void**)&blksum, g_blksum);
    cudaGetSymbolAddress((void**)&blkoff, g_blkoff);
    cudaGetSymbolAddress((void**)&dinv,   g_dinv);
    cudaGetSymbolAddress((void**)&gsum,   g_gsum);
    cudaGetSymbolAddress((void**)&gcnt,   g_gcnt);

    cudaFuncSetAttribute(gemm_scaled, cudaFuncAttributeMaxDynamicSharedMemorySize, GEMM_SMEM);

    const int NB_SCAN = (NN + 1023) / 1024;   // 98

    // CSR build (dinv fused into scan1); gemm L0 placed at launch #6 for ncu -s 5
    fill_zero<<<(NN / 4 + 255) / 256, 256>>>((float*)cnt, NN / 4);           // 1
    count_kernel<<<(NE + 255) / 256, 256>>>(ei, cnt);                        // 2
    scan1<<<NB_SCAN, 1024>>>(cnt, rowptr, blksum, dinv);                     // 3
    scan2<<<1, 128>>>(blksum, blkoff, NB_SCAN);                              // 4
    scan3<<<(NN + 255) / 256, 256>>>(rowptr, blkoff, cursor);                // 5
    gemm_scaled<<<NN / 32, 256, GEMM_SMEM>>>(x, conv_w, dinv, bufA);         // 6 (profiled)
    csr_fill<<<(NE + 255) / 256, 256>>>(ei, cursor, csr);                    // 7
    gather_combine<<<(NN * 32 + 255) / 256, 256>>>(rowptr, csr, bufA, dinv, conv_b, bufB); // 8

    const float* X = bufB;
    for (int l = 1; l < NCONV; l++) {
        gemm_scaled<<<NN / 32, 256, GEMM_SMEM>>>(X, conv_w + (size_t)l * F * F, dinv, bufA);
        gather_combine<<<(NN * 32 + 255) / 256, 256>>>(rowptr, csr, bufA, dinv,
                                                       conv_b + (size_t)l * F, bufB);
        X = bufB;
    }

    // global mean pool
    fill_zero<<<(NG * F / 4 + 255) / 256, 256>>>(gsum, NG * F / 4);
    fill_zero<<<1, 128>>>(gcnt, NG / 4);
    pool_kernel<<<(NN + 63) / 64, 128>>>(bufB, batch, gsum);
    cnt_kernel<<<(NN + 255) / 256, 256>>>(batch, gcnt);

    // head
    head_kernel<<<NG, 128>>>(gsum, gcnt, fc1w, fc1b, fc2w, fc2b, out);
}